// round 5
// baseline (speedup 1.0000x reference)
#include <cuda_runtime.h>
#include <cuda_bf16.h>
#include <cstdint>

#define B_DIM 4096
#define SPLIT 32
#define D_DIM 256
#define UNITS 256

#define MTILE 64
#define NTILE 256
#define KC 32
#define NSTAGE (D_DIM / KC)   // 8

// ---------------- smem layout ----------------
#define APITCH 144                      // bytes per 32-float tf32 row (128B data + 16B pad, ldsm conflict-free)
#define A_BUF (64 * APITCH)             // 9216
#define B_BUF (256 * APITCH)            // 36864
#define SM_A 0                          // 2 buffers -> 18432
#define SM_B (2 * A_BUF)
#define SM_TOTAL (2 * A_BUF + 2 * B_BUF)  // 92160 -> 2 CTAs/SM

// pre-converted W: tf32 bits, layout [s][n][k] (k contiguous)
__device__ __align__(16) uint32_t g_Wt[SPLIT * UNITS * D_DIM];

// ---------------- helpers ----------------
__device__ __forceinline__ uint32_t smem_u32(const void* p) {
    uint32_t a;
    asm("{ .reg .u64 t; cvta.to.shared.u64 t, %1; cvt.u32.u64 %0, t; }" : "=r"(a) : "l"(p));
    return a;
}

#define STS128(addr, v) \
    asm volatile("st.shared.v4.b32 [%0], {%1,%2,%3,%4};" :: "r"(addr), "r"((v).x), "r"((v).y), "r"((v).z), "r"((v).w) : "memory")

__device__ __forceinline__ void cp16(uint32_t dst, const void* src) {
    asm volatile("cp.async.cg.shared.global [%0], [%1], 16;"
                 :: "r"(dst), "l"((unsigned long long)__cvta_generic_to_global(src)) : "memory");
}
#define CP_COMMIT() asm volatile("cp.async.commit_group;" ::: "memory")
#define CP_WAIT0()  asm volatile("cp.async.wait_group 0;" ::: "memory")

__device__ __forceinline__ void ldsm4(uint32_t* r, uint32_t addr) {
    asm volatile("ldmatrix.sync.aligned.m8n8.x4.shared.b16 {%0,%1,%2,%3}, [%4];"
                 : "=r"(r[0]), "=r"(r[1]), "=r"(r[2]), "=r"(r[3]) : "r"(addr));
}

__device__ __forceinline__ void mma_tf32(float* d, const uint32_t* a, uint32_t b0, uint32_t b1) {
    asm volatile("mma.sync.aligned.m16n8k8.row.col.f32.tf32.tf32.f32 "
                 "{%0,%1,%2,%3}, {%4,%5,%6,%7}, {%8,%9}, {%0,%1,%2,%3};"
                 : "+f"(d[0]), "+f"(d[1]), "+f"(d[2]), "+f"(d[3])
                 : "r"(a[0]), "r"(a[1]), "r"(a[2]), "r"(a[3]), "r"(b0), "r"(b1));
}

__device__ __forceinline__ uint32_t f2tf32(float f) {
    uint32_t u;
    asm("cvt.rna.tf32.f32 %0, %1;" : "=r"(u) : "f"(f));
    return u;
}

// ---------------- prep kernel: W[s][k][n] fp32 -> g_Wt [s][n][k] tf32 ----------------
__global__ void prep_w_kernel(const float* __restrict__ W) {
    __shared__ float tile[32][33];
    int s = blockIdx.z;
    int kb = blockIdx.y * 32;
    int nb = blockIdx.x * 32;
    int tx = threadIdx.x, ty = threadIdx.y;
    const float* Ws = W + (size_t)s * D_DIM * UNITS;
#pragma unroll
    for (int i = 0; i < 4; i++) {
        int k = kb + ty + 8 * i;
        tile[ty + 8 * i][tx] = Ws[(size_t)k * UNITS + nb + tx];
    }
    __syncthreads();
#pragma unroll
    for (int i = 0; i < 4; i++) {
        int n = nb + ty + 8 * i;
        int k = kb + tx;
        g_Wt[((size_t)s * UNITS + n) * D_DIM + k] = f2tf32(tile[tx][ty + 8 * i]);
    }
}

// ---------------- main GEMM kernel (TF32 single-pass, 2 CTAs/SM) ----------------
__global__ void __launch_bounds__(256, 2) lc_tf32_kernel(
    const float* __restrict__ x, const float* __restrict__ bias, float* __restrict__ out) {
    extern __shared__ char smem[];
    uint32_t sb = smem_u32(smem);
    int tid = threadIdx.x;
    int wid = tid >> 5, lid = tid & 31;
    int mb = blockIdx.x;     // batch tile (fastest -> W slice L2 reuse)
    int s  = blockIdx.y;     // split
    int wm = wid >> 2;       // 0..1 : m half (32 rows)
    int wn = wid & 3;        // 0..3 : n quarter (64 cols)

    float acc[2][8][4];
#pragma unroll
    for (int i = 0; i < 2; i++)
#pragma unroll
        for (int j = 0; j < 8; j++)
#pragma unroll
            for (int v = 0; v < 4; v++) acc[i][j][v] = 0.f;

    // A staging: thread -> (row tid/4, 8-float quarter tid%4)
    int arow = tid >> 2, aq = tid & 3;
    const float* xsrc = x + (((size_t)(mb * MTILE + arow) * SPLIT + s) * D_DIM) + aq * 8;
    uint32_t asts = sb + SM_A + (uint32_t)(arow * APITCH + aq * 32);

    // B staging: thread -> n-row tid, 8x cp16 per chunk
    const uint32_t* wtsrc = g_Wt + ((size_t)s * UNITS + tid) * D_DIM;
    uint32_t bsts = sb + SM_B + (uint32_t)(tid * APITCH);

    // ldsm lane offsets (16 rows x 32B window; lane L -> row L%16, 16B-half L/16)
    uint32_t a_off = (uint32_t)((wm * 32 + (lid & 15)) * APITCH + (lid >> 4) * 16);
    uint32_t b_off = (uint32_t)((wn * 64 + (lid & 15)) * APITCH + (lid >> 4) * 16);

    float4 xa[2];

    // ---- prologue: stage chunk 0 ----
    xa[0] = __ldg((const float4*)xsrc);
    xa[1] = __ldg((const float4*)xsrc + 1);
    {
        uint4 u0 = make_uint4(f2tf32(xa[0].x), f2tf32(xa[0].y), f2tf32(xa[0].z), f2tf32(xa[0].w));
        uint4 u1 = make_uint4(f2tf32(xa[1].x), f2tf32(xa[1].y), f2tf32(xa[1].z), f2tf32(xa[1].w));
        STS128(asts, u0);
        STS128(asts + 16, u1);
    }
#pragma unroll
    for (int i = 0; i < 8; i++) cp16(bsts + i * 16, wtsrc + i * 4);
    CP_COMMIT();
    xa[0] = __ldg((const float4*)(xsrc + KC));
    xa[1] = __ldg((const float4*)(xsrc + KC) + 1);
    CP_WAIT0();
    __syncthreads();

    // ---- main loop over 8 K-chunks ----
#pragma unroll 1
    for (int kc = 0; kc < NSTAGE; kc++) {
        int cur = kc & 1;
        int nxt = cur ^ 1;

        if (kc < NSTAGE - 1) {
            // B cp.async for chunk kc+1
            uint32_t bd = bsts + (uint32_t)(nxt * B_BUF);
            const uint32_t* wt = wtsrc + (kc + 1) * KC;
#pragma unroll
            for (int i = 0; i < 8; i++) cp16(bd + i * 16, wt + i * 4);
            CP_COMMIT();
            // A cvt + STS for chunk kc+1 (regs prefetched)
            uint4 u0 = make_uint4(f2tf32(xa[0].x), f2tf32(xa[0].y), f2tf32(xa[0].z), f2tf32(xa[0].w));
            uint4 u1 = make_uint4(f2tf32(xa[1].x), f2tf32(xa[1].y), f2tf32(xa[1].z), f2tf32(xa[1].w));
            uint32_t ad = asts + (uint32_t)(nxt * A_BUF);
            STS128(ad, u0);
            STS128(ad + 16, u1);
        }
        if (kc < NSTAGE - 2) {
            xa[0] = __ldg((const float4*)(xsrc + (kc + 2) * KC));
            xa[1] = __ldg((const float4*)(xsrc + (kc + 2) * KC) + 1);
        }

        // ---- compute on buffer cur: 4 k8 steps ----
        uint32_t abase = sb + SM_A + (uint32_t)(cur * A_BUF) + a_off;
        uint32_t bbase = sb + SM_B + (uint32_t)(cur * B_BUF) + b_off;
#pragma unroll
        for (int ks = 0; ks < 4; ks++) {
            uint32_t af[2][4];
            uint32_t bf4[4][4];
#pragma unroll
            for (int mf = 0; mf < 2; mf++) ldsm4(af[mf], abase + mf * 16 * APITCH + ks * 32);
#pragma unroll
            for (int p = 0; p < 4; p++) ldsm4(bf4[p], bbase + p * 16 * APITCH + ks * 32);
#pragma unroll
            for (int mf = 0; mf < 2; mf++)
#pragma unroll
                for (int p = 0; p < 4; p++) {
                    mma_tf32(acc[mf][2 * p],     af[mf], bf4[p][0], bf4[p][2]);  // n sub-block 0-7
                    mma_tf32(acc[mf][2 * p + 1], af[mf], bf4[p][1], bf4[p][3]);  // n sub-block 8-15
                }
        }

        if (kc < NSTAGE - 1) {
            CP_WAIT0();
            __syncthreads();
        }
    }

    // ---- epilogue: bias + relu + store ----
    const float* brow = bias + s * UNITS;
#pragma unroll
    for (int mf = 0; mf < 2; mf++) {
        int r0 = mb * MTILE + wm * 32 + mf * 16 + (lid >> 2);
        float* o0 = out + ((size_t)r0 * SPLIT + s) * UNITS;
        float* o1 = o0 + (size_t)8 * SPLIT * UNITS;
#pragma unroll
        for (int nf = 0; nf < 8; nf++) {
            int c = wn * 64 + nf * 8 + 2 * (lid & 3);
            float2 bv = *(const float2*)(brow + c);
            float2 v0, v1;
            v0.x = fmaxf(acc[mf][nf][0] + bv.x, 0.f);
            v0.y = fmaxf(acc[mf][nf][1] + bv.y, 0.f);
            v1.x = fmaxf(acc[mf][nf][2] + bv.x, 0.f);
            v1.y = fmaxf(acc[mf][nf][3] + bv.y, 0.f);
            *(float2*)(o0 + c) = v0;
            *(float2*)(o1 + c) = v1;
        }
    }
}

// ---------------- launch ----------------
extern "C" void kernel_launch(void* const* d_in, const int* in_sizes, int n_in,
                              void* d_out, int out_size) {
    const float* x = (const float*)d_in[0];
    const float* W = (const float*)d_in[1];
    const float* b = (const float*)d_in[2];
    float* out = (float*)d_out;

    prep_w_kernel<<<dim3(8, 8, 32), dim3(32, 8)>>>(W);

    cudaFuncSetAttribute(lc_tf32_kernel, cudaFuncAttributeMaxDynamicSharedMemorySize, SM_TOTAL);
    lc_tf32_kernel<<<dim3(B_DIM / MTILE, SPLIT), 256, SM_TOTAL>>>(x, b, out);
}

// round 6
// speedup vs baseline: 1.5894x; 1.5894x over previous
#include <cuda_runtime.h>
#include <cuda_fp16.h>
#include <cstdint>

#define B_DIM 4096
#define SPLIT 32
#define D_DIM 256
#define UNITS 256

#define MTILE 128
#define NTILE 128
#define KC 32
#define NSTAGE (D_DIM / KC)   // 8

// ---------------- smem layout ----------------
#define APITCH 80                       // bytes per 32-elem fp16 row (64B data + 16B pad, ldsm conflict-free)
#define ABYTES (128 * APITCH)           // 10240 per term per buffer
#define BBYTES (128 * APITCH)           // 10240 per buffer
#define SM_A 0                          // (buf*2+term)*ABYTES -> 40960 total
#define SM_B 40960                      // buf*BBYTES -> 20480 total
#define SM_TOTAL (40960 + 20480)        // 61440 -> 2 CTAs/SM

// pre-converted W: fp16 bits, layout [s][n][k] (k contiguous)
__device__ __align__(16) unsigned short g_Wh[SPLIT * UNITS * D_DIM];

// ---------------- helpers ----------------
__device__ __forceinline__ uint32_t smem_u32(const void* p) {
    uint32_t a;
    asm("{ .reg .u64 t; cvta.to.shared.u64 t, %1; cvt.u32.u64 %0, t; }" : "=r"(a) : "l"(p));
    return a;
}

#define STS128(addr, v) \
    asm volatile("st.shared.v4.b32 [%0], {%1,%2,%3,%4};" :: "r"(addr), "r"((v).x), "r"((v).y), "r"((v).z), "r"((v).w) : "memory")

__device__ __forceinline__ void cp16(uint32_t dst, const void* src) {
    asm volatile("cp.async.cg.shared.global [%0], [%1], 16;"
                 :: "r"(dst), "l"((unsigned long long)__cvta_generic_to_global(src)) : "memory");
}
#define CP_COMMIT() asm volatile("cp.async.commit_group;" ::: "memory")
#define CP_WAIT0()  asm volatile("cp.async.wait_group 0;" ::: "memory")

__device__ __forceinline__ void ldsm4(uint32_t* r, uint32_t addr) {
    asm volatile("ldmatrix.sync.aligned.m8n8.x4.shared.b16 {%0,%1,%2,%3}, [%4];"
                 : "=r"(r[0]), "=r"(r[1]), "=r"(r[2]), "=r"(r[3]) : "r"(addr));
}

__device__ __forceinline__ void mma_f16(float* d, const uint32_t* a, const uint32_t* b) {
    asm volatile("mma.sync.aligned.m16n8k16.row.col.f32.f16.f16.f32 "
                 "{%0,%1,%2,%3}, {%4,%5,%6,%7}, {%8,%9}, {%0,%1,%2,%3};"
                 : "+f"(d[0]), "+f"(d[1]), "+f"(d[2]), "+f"(d[3])
                 : "r"(a[0]), "r"(a[1]), "r"(a[2]), "r"(a[3]), "r"(b[0]), "r"(b[1]));
}

// split 8 fp32 -> packed fp16 hi (rn) and fp16 lo (rn of residual; residual exact in fp32)
__device__ __forceinline__ void split8(const float4 a, const float4 c, uint4& hi, uint4& lo) {
    float fa[8] = { a.x, a.y, a.z, a.w, c.x, c.y, c.z, c.w };
    uint32_t h[4], l[4];
#pragma unroll
    for (int i = 0; i < 4; i++) {
        float f0 = fa[2 * i], f1 = fa[2 * i + 1];
        uint32_t hp;
        asm("cvt.rn.f16x2.f32 %0, %1, %2;" : "=r"(hp) : "f"(f1), "f"(f0)); // lo16 = f16(f0), hi16 = f16(f1)
        h[i] = hp;
        __half h0 = __ushort_as_half((unsigned short)(hp & 0xffffu));
        __half h1 = __ushort_as_half((unsigned short)(hp >> 16));
        float r0 = f0 - __half2float(h0);
        float r1 = f1 - __half2float(h1);
        uint32_t lp;
        asm("cvt.rn.f16x2.f32 %0, %1, %2;" : "=r"(lp) : "f"(r1), "f"(r0));
        l[i] = lp;
    }
    hi = make_uint4(h[0], h[1], h[2], h[3]);
    lo = make_uint4(l[0], l[1], l[2], l[3]);
}

// ---------------- prep kernel: W[s][k][n] fp32 -> g_Wh [s][n][k] fp16 ----------------
__global__ void prep_w_kernel(const float* __restrict__ W) {
    __shared__ float tile[32][33];
    int s = blockIdx.z;
    int kb = blockIdx.y * 32;
    int nb = blockIdx.x * 32;
    int tx = threadIdx.x, ty = threadIdx.y;
    const float* Ws = W + (size_t)s * D_DIM * UNITS;
#pragma unroll
    for (int i = 0; i < 4; i++) {
        int k = kb + ty + 8 * i;
        tile[ty + 8 * i][tx] = Ws[(size_t)k * UNITS + nb + tx];
    }
    __syncthreads();
#pragma unroll
    for (int i = 0; i < 4; i++) {
        int n = nb + ty + 8 * i;
        int k = kb + tx;
        g_Wh[((size_t)s * UNITS + n) * D_DIM + k] =
            __half_as_ushort(__float2half_rn(tile[tx][ty + 8 * i]));
    }
}

// ---------------- main GEMM kernel (fp16 HMMA, 2-term x split, 2 CTAs/SM) ----------------
__global__ void __launch_bounds__(256, 2) lc_hmma_kernel(
    const float* __restrict__ x, const float* __restrict__ bias, float* __restrict__ out) {
    extern __shared__ char smem[];
    uint32_t sb = smem_u32(smem);
    int tid = threadIdx.x;
    int wid = tid >> 5, lid = tid & 31;
    int mb = blockIdx.x;     // batch tile (fastest -> W slice L2 reuse)
    int s  = blockIdx.y;     // split
    int nb = blockIdx.z;     // n half
    int wm = wid >> 2;       // 0..1 : m half (64 rows)
    int wn = wid & 3;        // 0..3 : n quarter (32 cols)

    float acc[4][4][4];
#pragma unroll
    for (int i = 0; i < 4; i++)
#pragma unroll
        for (int j = 0; j < 4; j++)
#pragma unroll
            for (int v = 0; v < 4; v++) acc[i][j][v] = 0.f;

    // A staging: thread -> (row, 16-float half)
    int arow = tid >> 1, ahalf = tid & 1;
    const float* xbase = x + (((size_t)(mb * MTILE + arow) * SPLIT + s) * D_DIM) + ahalf * 16;
    uint32_t asts = sb + SM_A + (uint32_t)(arow * APITCH + ahalf * 32);

    // B staging: thread -> (n-row, 16-elem half), 2 cp16 total
    const unsigned short* whsrc = g_Wh + ((size_t)s * UNITS + nb * NTILE + arow) * D_DIM + ahalf * 16;
    uint32_t bsts = sb + SM_B + (uint32_t)(arow * APITCH + ahalf * 32);

    // ldmatrix lane offsets
    uint32_t a_off = (uint32_t)((wm * 64 + (lid & 7) + ((lid >> 3) & 1) * 8) * APITCH + (lid >> 4) * 16);
    uint32_t b_off = (uint32_t)((wn * 32 + (lid & 7) + ((lid >> 4) & 1) * 8) * APITCH + ((lid >> 3) & 1) * 16);

    float4 xa[4];

    // ---- prologue: stage chunk 0 ----
#pragma unroll
    for (int j = 0; j < 4; j++) xa[j] = __ldg((const float4*)(xbase) + j);
    {
        uint4 h0, l0, h1, l1;
        split8(xa[0], xa[1], h0, l0);
        split8(xa[2], xa[3], h1, l1);
        STS128(asts, h0);          STS128(asts + 16, h1);
        STS128(asts + ABYTES, l0); STS128(asts + ABYTES + 16, l1);
    }
    cp16(bsts,      whsrc);
    cp16(bsts + 16, whsrc + 8);
    CP_COMMIT();
#pragma unroll
    for (int j = 0; j < 4; j++) xa[j] = __ldg((const float4*)(xbase + KC) + j);
    CP_WAIT0();
    __syncthreads();

    // ---- main loop over 8 K-chunks ----
#pragma unroll 1
    for (int kc = 0; kc < NSTAGE; kc++) {
        int cur = kc & 1;
        int nxt = cur ^ 1;

        if (kc < NSTAGE - 1) {
            uint32_t bd = bsts + (uint32_t)(nxt * BBYTES);
            const unsigned short* wh = whsrc + (kc + 1) * KC;
            cp16(bd,      wh);
            cp16(bd + 16, wh + 8);
            CP_COMMIT();
            uint4 h0, l0, h1, l1;
            split8(xa[0], xa[1], h0, l0);
            split8(xa[2], xa[3], h1, l1);
            uint32_t ad = asts + (uint32_t)(nxt * 2 * ABYTES);
            STS128(ad, h0);          STS128(ad + 16, h1);
            STS128(ad + ABYTES, l0); STS128(ad + ABYTES + 16, l1);
        }
        if (kc < NSTAGE - 2) {
#pragma unroll
            for (int j = 0; j < 4; j++) xa[j] = __ldg((const float4*)(xbase + (kc + 2) * KC) + j);
        }

        // ---- compute on buffer cur: K=32 -> 2 k16 steps, 2 terms ----
        uint32_t abase = sb + SM_A + (uint32_t)(cur * 2 * ABYTES) + a_off;
        uint32_t bbase = sb + SM_B + (uint32_t)(cur * BBYTES) + b_off;
#pragma unroll
        for (int ks = 0; ks < 2; ks++) {
            uint32_t ab = abase + ks * 32;
            uint32_t bb = bbase + ks * 32;
            uint32_t ah[16], bh[8];
#pragma unroll
            for (int mf = 0; mf < 4; mf++) ldsm4(&ah[4 * mf], ab + mf * 16 * APITCH);
#pragma unroll
            for (int p = 0; p < 2; p++) ldsm4(&bh[4 * p], bb + p * 16 * APITCH);
            // term 1: xhi * W
#pragma unroll
            for (int mf = 0; mf < 4; mf++)
#pragma unroll
                for (int nf = 0; nf < 4; nf++) mma_f16(acc[mf][nf], &ah[4 * mf], &bh[2 * nf]);
            // term 2: xlo * W (reuse ah regs for alo)
#pragma unroll
            for (int mf = 0; mf < 4; mf++) ldsm4(&ah[4 * mf], ab + ABYTES + mf * 16 * APITCH);
#pragma unroll
            for (int mf = 0; mf < 4; mf++)
#pragma unroll
                for (int nf = 0; nf < 4; nf++) mma_f16(acc[mf][nf], &ah[4 * mf], &bh[2 * nf]);
        }

        if (kc < NSTAGE - 1) {
            CP_WAIT0();
            __syncthreads();
        }
    }

    // ---- epilogue: bias + relu + store ----
    const float* brow = bias + s * UNITS + nb * NTILE;
#pragma unroll
    for (int mf = 0; mf < 4; mf++) {
        int r0 = mb * MTILE + wm * 64 + mf * 16 + (lid >> 2);
        float* o0 = out + ((size_t)r0 * SPLIT + s) * UNITS + nb * NTILE;
        float* o1 = o0 + (size_t)8 * SPLIT * UNITS;
#pragma unroll
        for (int nf = 0; nf < 4; nf++) {
            int c = wn * 32 + nf * 8 + 2 * (lid & 3);
            float2 bv = *(const float2*)(brow + c);
            float2 v0, v1;
            v0.x = fmaxf(acc[mf][nf][0] + bv.x, 0.f);
            v0.y = fmaxf(acc[mf][nf][1] + bv.y, 0.f);
            v1.x = fmaxf(acc[mf][nf][2] + bv.x, 0.f);
            v1.y = fmaxf(acc[mf][nf][3] + bv.y, 0.f);
            *(float2*)(o0 + c) = v0;
            *(float2*)(o1 + c) = v1;
        }
    }
}

// ---------------- launch ----------------
extern "C" void kernel_launch(void* const* d_in, const int* in_sizes, int n_in,
                              void* d_out, int out_size) {
    const float* x = (const float*)d_in[0];
    const float* W = (const float*)d_in[1];
    const float* b = (const float*)d_in[2];
    float* out = (float*)d_out;

    prep_w_kernel<<<dim3(8, 8, 32), dim3(32, 8)>>>(W);

    cudaFuncSetAttribute(lc_hmma_kernel, cudaFuncAttributeMaxDynamicSharedMemorySize, SM_TOTAL);
    lc_hmma_kernel<<<dim3(B_DIM / MTILE, SPLIT, UNITS / NTILE), 256, SM_TOTAL>>>(x, b, out);
}

// round 7
// speedup vs baseline: 1.8624x; 1.1718x over previous
#include <cuda_runtime.h>
#include <cuda_fp16.h>
#include <cstdint>

#define B_DIM 4096
#define SPLIT 32
#define D_DIM 256
#define UNITS 256

#define MTILE 128
#define NTILE 128
#define KC 32
#define NSTAGE (D_DIM / KC)   // 8

// ---------------- smem layout ----------------
#define APITCH 80                       // bytes per 32-elem fp16 row (64B data + 16B pad, ldsm conflict-free)
#define ABYTES (128 * APITCH)           // 10240 per buffer
#define BBYTES (128 * APITCH)           // 10240 per buffer
#define SM_A 0                          // 2 buffers -> 20480
#define SM_B 20480                      // 2 buffers -> 20480
#define SM_TOTAL (20480 + 20480)        // 40960 -> 2 CTAs/SM (reg-limited)

// pre-converted W: fp16 bits, layout [s][n][k] (k contiguous)
__device__ __align__(16) unsigned short g_Wh[SPLIT * UNITS * D_DIM];

// ---------------- helpers ----------------
__device__ __forceinline__ uint32_t smem_u32(const void* p) {
    uint32_t a;
    asm("{ .reg .u64 t; cvta.to.shared.u64 t, %1; cvt.u32.u64 %0, t; }" : "=r"(a) : "l"(p));
    return a;
}

#define STS128(addr, v) \
    asm volatile("st.shared.v4.b32 [%0], {%1,%2,%3,%4};" :: "r"(addr), "r"((v).x), "r"((v).y), "r"((v).z), "r"((v).w) : "memory")

__device__ __forceinline__ void cp16(uint32_t dst, const void* src) {
    asm volatile("cp.async.cg.shared.global [%0], [%1], 16;"
                 :: "r"(dst), "l"((unsigned long long)__cvta_generic_to_global(src)) : "memory");
}
#define CP_COMMIT() asm volatile("cp.async.commit_group;" ::: "memory")
#define CP_WAIT0()  asm volatile("cp.async.wait_group 0;" ::: "memory")

__device__ __forceinline__ void ldsm4(uint32_t* r, uint32_t addr) {
    asm volatile("ldmatrix.sync.aligned.m8n8.x4.shared.b16 {%0,%1,%2,%3}, [%4];"
                 : "=r"(r[0]), "=r"(r[1]), "=r"(r[2]), "=r"(r[3]) : "r"(addr));
}

__device__ __forceinline__ void mma_f16(float* d, const uint32_t* a, const uint32_t* b) {
    asm volatile("mma.sync.aligned.m16n8k16.row.col.f32.f16.f16.f32 "
                 "{%0,%1,%2,%3}, {%4,%5,%6,%7}, {%8,%9}, {%0,%1,%2,%3};"
                 : "+f"(d[0]), "+f"(d[1]), "+f"(d[2]), "+f"(d[3])
                 : "r"(a[0]), "r"(a[1]), "r"(a[2]), "r"(a[3]), "r"(b[0]), "r"(b[1]));
}

// convert 8 fp32 -> 8 packed fp16 (rn)
__device__ __forceinline__ void cvt8(const float4 a, const float4 c, uint4& h) {
    uint32_t p0, p1, p2, p3;
    asm("cvt.rn.f16x2.f32 %0, %1, %2;" : "=r"(p0) : "f"(a.y), "f"(a.x));
    asm("cvt.rn.f16x2.f32 %0, %1, %2;" : "=r"(p1) : "f"(a.w), "f"(a.z));
    asm("cvt.rn.f16x2.f32 %0, %1, %2;" : "=r"(p2) : "f"(c.y), "f"(c.x));
    asm("cvt.rn.f16x2.f32 %0, %1, %2;" : "=r"(p3) : "f"(c.w), "f"(c.z));
    h = make_uint4(p0, p1, p2, p3);
}

// ---------------- prep kernel: W[s][k][n] fp32 -> g_Wh [s][n][k] fp16 ----------------
__global__ void prep_w_kernel(const float* __restrict__ W) {
    __shared__ float tile[32][33];
    int s = blockIdx.z;
    int kb = blockIdx.y * 32;
    int nb = blockIdx.x * 32;
    int tx = threadIdx.x, ty = threadIdx.y;
    const float* Ws = W + (size_t)s * D_DIM * UNITS;
#pragma unroll
    for (int i = 0; i < 4; i++) {
        int k = kb + ty + 8 * i;
        tile[ty + 8 * i][tx] = Ws[(size_t)k * UNITS + nb + tx];
    }
    __syncthreads();
#pragma unroll
    for (int i = 0; i < 4; i++) {
        int n = nb + ty + 8 * i;
        int k = kb + tx;
        g_Wh[((size_t)s * UNITS + n) * D_DIM + k] =
            __half_as_ushort(__float2half_rn(tile[tx][ty + 8 * i]));
    }
}

// ---------------- main GEMM kernel (fp16 HMMA single-pass, 2 CTAs/SM) ----------------
__global__ void __launch_bounds__(256, 2) lc_hmma_kernel(
    const float* __restrict__ x, const float* __restrict__ bias, float* __restrict__ out) {
    extern __shared__ char smem[];
    uint32_t sb = smem_u32(smem);
    int tid = threadIdx.x;
    int wid = tid >> 5, lid = tid & 31;
    int mb = blockIdx.x;     // batch tile (fastest -> W slice L2 reuse)
    int s  = blockIdx.y;     // split
    int nb = blockIdx.z;     // n half
    int wm = wid >> 2;       // 0..1 : m half (64 rows)
    int wn = wid & 3;        // 0..3 : n quarter (32 cols)

    float acc[4][4][4];
#pragma unroll
    for (int i = 0; i < 4; i++)
#pragma unroll
        for (int j = 0; j < 4; j++)
#pragma unroll
            for (int v = 0; v < 4; v++) acc[i][j][v] = 0.f;

    // A staging: thread -> (row, 16-float half)
    int arow = tid >> 1, ahalf = tid & 1;
    const float* xbase = x + (((size_t)(mb * MTILE + arow) * SPLIT + s) * D_DIM) + ahalf * 16;
    uint32_t asts = sb + SM_A + (uint32_t)(arow * APITCH + ahalf * 32);

    // B staging: thread -> (n-row, 16-elem half), 2 cp16 total
    const unsigned short* whsrc = g_Wh + ((size_t)s * UNITS + nb * NTILE + arow) * D_DIM + ahalf * 16;
    uint32_t bsts = sb + SM_B + (uint32_t)(arow * APITCH + ahalf * 32);

    // ldmatrix lane offsets
    uint32_t a_off = (uint32_t)((wm * 64 + (lid & 7) + ((lid >> 3) & 1) * 8) * APITCH + (lid >> 4) * 16);
    uint32_t b_off = (uint32_t)((wn * 32 + (lid & 7) + ((lid >> 4) & 1) * 8) * APITCH + ((lid >> 3) & 1) * 16);

    float4 xa[4];

    // ---- prologue: stage chunk 0 ----
#pragma unroll
    for (int j = 0; j < 4; j++) xa[j] = __ldg((const float4*)(xbase) + j);
    {
        uint4 h0, h1;
        cvt8(xa[0], xa[1], h0);
        cvt8(xa[2], xa[3], h1);
        STS128(asts, h0);
        STS128(asts + 16, h1);
    }
    cp16(bsts,      whsrc);
    cp16(bsts + 16, whsrc + 8);
    CP_COMMIT();
#pragma unroll
    for (int j = 0; j < 4; j++) xa[j] = __ldg((const float4*)(xbase + KC) + j);
    CP_WAIT0();
    __syncthreads();

    // ---- main loop over 8 K-chunks ----
#pragma unroll 1
    for (int kc = 0; kc < NSTAGE; kc++) {
        int cur = kc & 1;
        int nxt = cur ^ 1;

        if (kc < NSTAGE - 1) {
            uint32_t bd = bsts + (uint32_t)(nxt * BBYTES);
            const unsigned short* wh = whsrc + (kc + 1) * KC;
            cp16(bd,      wh);
            cp16(bd + 16, wh + 8);
            CP_COMMIT();
            uint4 h0, h1;
            cvt8(xa[0], xa[1], h0);
            cvt8(xa[2], xa[3], h1);
            uint32_t ad = asts + (uint32_t)(nxt * ABYTES);
            STS128(ad, h0);
            STS128(ad + 16, h1);
        }
        if (kc < NSTAGE - 2) {
#pragma unroll
            for (int j = 0; j < 4; j++) xa[j] = __ldg((const float4*)(xbase + (kc + 2) * KC) + j);
        }

        // ---- compute on buffer cur: K=32 -> 2 k16 steps, 1 term ----
        uint32_t abase = sb + SM_A + (uint32_t)(cur * ABYTES) + a_off;
        uint32_t bbase = sb + SM_B + (uint32_t)(cur * BBYTES) + b_off;
#pragma unroll
        for (int ks = 0; ks < 2; ks++) {
            uint32_t ab = abase + ks * 32;
            uint32_t bb = bbase + ks * 32;
            uint32_t ah[16], bh[8];
#pragma unroll
            for (int mf = 0; mf < 4; mf++) ldsm4(&ah[4 * mf], ab + mf * 16 * APITCH);
#pragma unroll
            for (int p = 0; p < 2; p++) ldsm4(&bh[4 * p], bb + p * 16 * APITCH);
#pragma unroll
            for (int mf = 0; mf < 4; mf++)
#pragma unroll
                for (int nf = 0; nf < 4; nf++) mma_f16(acc[mf][nf], &ah[4 * mf], &bh[2 * nf]);
        }

        if (kc < NSTAGE - 1) {
            CP_WAIT0();
            __syncthreads();
        }
    }

    // ---- epilogue: bias + relu + store ----
    const float* brow = bias + s * UNITS + nb * NTILE;
#pragma unroll
    for (int mf = 0; mf < 4; mf++) {
        int r0 = mb * MTILE + wm * 64 + mf * 16 + (lid >> 2);
        float* o0 = out + ((size_t)r0 * SPLIT + s) * UNITS + nb * NTILE;
        float* o1 = o0 + (size_t)8 * SPLIT * UNITS;
#pragma unroll
        for (int nf = 0; nf < 4; nf++) {
            int c = wn * 32 + nf * 8 + 2 * (lid & 3);
            float2 bv = *(const float2*)(brow + c);
            float2 v0, v1;
            v0.x = fmaxf(acc[mf][nf][0] + bv.x, 0.f);
            v0.y = fmaxf(acc[mf][nf][1] + bv.y, 0.f);
            v1.x = fmaxf(acc[mf][nf][2] + bv.x, 0.f);
            v1.y = fmaxf(acc[mf][nf][3] + bv.y, 0.f);
            *(float2*)(o0 + c) = v0;
            *(float2*)(o1 + c) = v1;
        }
    }
}

// ---------------- launch ----------------
extern "C" void kernel_launch(void* const* d_in, const int* in_sizes, int n_in,
                              void* d_out, int out_size) {
    const float* x = (const float*)d_in[0];
    const float* W = (const float*)d_in[1];
    const float* b = (const float*)d_in[2];
    float* out = (float*)d_out;

    prep_w_kernel<<<dim3(8, 8, 32), dim3(32, 8)>>>(W);

    cudaFuncSetAttribute(lc_hmma_kernel, cudaFuncAttributeMaxDynamicSharedMemorySize, SM_TOTAL);
    lc_hmma_kernel<<<dim3(B_DIM / MTILE, SPLIT, UNITS / NTILE), 256, SM_TOTAL>>>(x, b, out);
}

// round 8
// speedup vs baseline: 2.0218x; 1.0856x over previous
#include <cuda_runtime.h>
#include <cuda_fp16.h>
#include <cstdint>

#define B_DIM 4096
#define SPLIT 32
#define D_DIM 256
#define UNITS 256

#define MTILE 128
#define NTILE 128
#define KC 32
#define NSTAGE (D_DIM / KC)   // 8

// ---------------- smem layout ----------------
#define APITCH 80                       // bytes per 32-elem fp16 row (64B data + 16B pad, ldsm conflict-free)
#define ABYTES (128 * APITCH)           // 10240 per buffer (2 buffers)
#define BBYTES (128 * APITCH)           // 10240 per buffer (3 buffers)
#define SM_A 0                          // 2 buffers -> 20480
#define SM_B 20480                      // 3 buffers -> 30720
#define SM_TOTAL (20480 + 30720)        // 51200 -> 2 CTAs/SM (reg-limited)

// pre-converted W: fp16 bits, layout [s][n][k] (k contiguous)
__device__ __align__(16) unsigned short g_Wh[SPLIT * UNITS * D_DIM];

// ---------------- helpers ----------------
__device__ __forceinline__ uint32_t smem_u32(const void* p) {
    uint32_t a;
    asm("{ .reg .u64 t; cvta.to.shared.u64 t, %1; cvt.u32.u64 %0, t; }" : "=r"(a) : "l"(p));
    return a;
}

#define STS128(addr, v) \
    asm volatile("st.shared.v4.b32 [%0], {%1,%2,%3,%4};" :: "r"(addr), "r"((v).x), "r"((v).y), "r"((v).z), "r"((v).w) : "memory")

__device__ __forceinline__ void cp16(uint32_t dst, const void* src) {
    asm volatile("cp.async.cg.shared.global [%0], [%1], 16;"
                 :: "r"(dst), "l"((unsigned long long)__cvta_generic_to_global(src)) : "memory");
}
#define CP_COMMIT() asm volatile("cp.async.commit_group;" ::: "memory")
#define CP_WAIT1()  asm volatile("cp.async.wait_group 1;" ::: "memory")
#define CP_WAIT0()  asm volatile("cp.async.wait_group 0;" ::: "memory")

__device__ __forceinline__ void ldsm4(uint32_t* r, uint32_t addr) {
    asm volatile("ldmatrix.sync.aligned.m8n8.x4.shared.b16 {%0,%1,%2,%3}, [%4];"
                 : "=r"(r[0]), "=r"(r[1]), "=r"(r[2]), "=r"(r[3]) : "r"(addr));
}

__device__ __forceinline__ void mma_f16(float* d, const uint32_t* a, const uint32_t* b) {
    asm volatile("mma.sync.aligned.m16n8k16.row.col.f32.f16.f16.f32 "
                 "{%0,%1,%2,%3}, {%4,%5,%6,%7}, {%8,%9}, {%0,%1,%2,%3};"
                 : "+f"(d[0]), "+f"(d[1]), "+f"(d[2]), "+f"(d[3])
                 : "r"(a[0]), "r"(a[1]), "r"(a[2]), "r"(a[3]), "r"(b[0]), "r"(b[1]));
}

// convert 8 fp32 -> 8 packed fp16 (rn)
__device__ __forceinline__ void cvt8(const float4 a, const float4 c, uint4& h) {
    uint32_t p0, p1, p2, p3;
    asm("cvt.rn.f16x2.f32 %0, %1, %2;" : "=r"(p0) : "f"(a.y), "f"(a.x));
    asm("cvt.rn.f16x2.f32 %0, %1, %2;" : "=r"(p1) : "f"(a.w), "f"(a.z));
    asm("cvt.rn.f16x2.f32 %0, %1, %2;" : "=r"(p2) : "f"(c.y), "f"(c.x));
    asm("cvt.rn.f16x2.f32 %0, %1, %2;" : "=r"(p3) : "f"(c.w), "f"(c.z));
    h = make_uint4(p0, p1, p2, p3);
}

// ---------------- prep kernel: W[s][k][n] fp32 -> g_Wh [s][n][k] fp16 ----------------
__global__ void prep_w_kernel(const float* __restrict__ W) {
    __shared__ float tile[32][33];
    int s = blockIdx.z;
    int kb = blockIdx.y * 32;
    int nb = blockIdx.x * 32;
    int tx = threadIdx.x, ty = threadIdx.y;
    const float* Ws = W + (size_t)s * D_DIM * UNITS;
#pragma unroll
    for (int i = 0; i < 4; i++) {
        int k = kb + ty + 8 * i;
        tile[ty + 8 * i][tx] = Ws[(size_t)k * UNITS + nb + tx];
    }
    __syncthreads();
#pragma unroll
    for (int i = 0; i < 4; i++) {
        int n = nb + ty + 8 * i;
        int k = kb + tx;
        g_Wh[((size_t)s * UNITS + n) * D_DIM + k] =
            __half_as_ushort(__float2half_rn(tile[tx][ty + 8 * i]));
    }
}

// ---------------- main GEMM kernel (fp16 HMMA, 3-stage B pipeline, 2 CTAs/SM) ----------------
__global__ void __launch_bounds__(256, 2) lc_hmma_kernel(
    const float* __restrict__ x, const float* __restrict__ bias, float* __restrict__ out) {
    extern __shared__ char smem[];
    uint32_t sb = smem_u32(smem);
    int tid = threadIdx.x;
    int wid = tid >> 5, lid = tid & 31;
    int mb = blockIdx.x >> 1;       // batch tile
    int nb = blockIdx.x & 1;        // n half (adjacent -> shared x slice hits L2)
    int s  = blockIdx.y;            // split
    int wm = wid >> 2;              // 0..1 : m half (64 rows)
    int wn = wid & 3;               // 0..3 : n quarter (32 cols)

    float acc[4][4][4];
#pragma unroll
    for (int i = 0; i < 4; i++)
#pragma unroll
        for (int j = 0; j < 4; j++)
#pragma unroll
            for (int v = 0; v < 4; v++) acc[i][j][v] = 0.f;

    // A staging: thread -> (row, 16-float half)
    int arow = tid >> 1, ahalf = tid & 1;
    const float* xbase = x + (((size_t)(mb * MTILE + arow) * SPLIT + s) * D_DIM) + ahalf * 16;
    uint32_t asts = sb + SM_A + (uint32_t)(arow * APITCH + ahalf * 32);

    // B staging: thread -> (n-row, 16-elem half), 2 cp16 per chunk
    const unsigned short* whsrc = g_Wh + ((size_t)s * UNITS + nb * NTILE + arow) * D_DIM + ahalf * 16;
    uint32_t bsts = sb + SM_B + (uint32_t)(arow * APITCH + ahalf * 32);

    // ldmatrix lane offsets
    uint32_t a_off = (uint32_t)((wm * 64 + (lid & 7) + ((lid >> 3) & 1) * 8) * APITCH + (lid >> 4) * 16);
    uint32_t b_off = (uint32_t)((wn * 32 + (lid & 7) + ((lid >> 4) & 1) * 8) * APITCH + ((lid >> 3) & 1) * 16);

    float4 xa[4];

    // ---- prologue ----
    // A chunk 0 -> buf 0
#pragma unroll
    for (int j = 0; j < 4; j++) xa[j] = __ldg((const float4*)(xbase) + j);
    {
        uint4 h0, h1;
        cvt8(xa[0], xa[1], h0);
        cvt8(xa[2], xa[3], h1);
        STS128(asts, h0);
        STS128(asts + 16, h1);
    }
    // B chunk 0 -> buf 0 (group 0)
    cp16(bsts,      whsrc);
    cp16(bsts + 16, whsrc + 8);
    CP_COMMIT();
    // B chunk 1 -> buf 1 (group 1)
    cp16(bsts + BBYTES,      whsrc + KC);
    cp16(bsts + BBYTES + 16, whsrc + KC + 8);
    CP_COMMIT();
    // A regs for chunk 1 (STS at kc=0)
#pragma unroll
    for (int j = 0; j < 4; j++) xa[j] = __ldg((const float4*)(xbase + KC) + j);
    CP_WAIT1();           // group 0 done
    __syncthreads();

    // ---- main loop over 8 K-chunks ----
    // B: buf kc%3; written 2 ahead via cp.async (wait_group 1 at bottom)
    // A: buf kc%2; STS 1 ahead from regs loaded 2 ahead
#pragma unroll 1
    for (int kc = 0; kc < NSTAGE; kc++) {
        // issue B cp.async for chunk kc+2
        if (kc + 2 < NSTAGE) {
            uint32_t bd = bsts + (uint32_t)(((kc + 2) % 3) * BBYTES);
            const unsigned short* wh = whsrc + (kc + 2) * KC;
            cp16(bd,      wh);
            cp16(bd + 16, wh + 8);
        }
        CP_COMMIT();   // always commit to keep group accounting uniform

        // A: cvt+STS chunk kc+1 (regs loaded at kc-1)
        if (kc + 1 < NSTAGE) {
            uint4 h0, h1;
            cvt8(xa[0], xa[1], h0);
            cvt8(xa[2], xa[3], h1);
            uint32_t ad = asts + (uint32_t)(((kc + 1) & 1) * ABYTES);
            STS128(ad, h0);
            STS128(ad + 16, h1);
        }
        // A: LDG regs for chunk kc+2
        if (kc + 2 < NSTAGE) {
#pragma unroll
            for (int j = 0; j < 4; j++) xa[j] = __ldg((const float4*)(xbase + (kc + 2) * KC) + j);
        }

        // ---- compute chunk kc ----
        uint32_t abase = sb + SM_A + (uint32_t)((kc & 1) * ABYTES) + a_off;
        uint32_t bbase = sb + SM_B + (uint32_t)((kc % 3) * BBYTES) + b_off;
#pragma unroll
        for (int ks = 0; ks < 2; ks++) {
            uint32_t ab = abase + ks * 32;
            uint32_t bb = bbase + ks * 32;
            uint32_t ah[16], bh[8];
#pragma unroll
            for (int mf = 0; mf < 4; mf++) ldsm4(&ah[4 * mf], ab + mf * 16 * APITCH);
#pragma unroll
            for (int p = 0; p < 2; p++) ldsm4(&bh[4 * p], bb + p * 16 * APITCH);
#pragma unroll
            for (int mf = 0; mf < 4; mf++)
#pragma unroll
                for (int nf = 0; nf < 4; nf++) mma_f16(acc[mf][nf], &ah[4 * mf], &bh[2 * nf]);
        }

        if (kc < NSTAGE - 1) {
            CP_WAIT1();        // group issued at kc-1 (chunk kc+1) complete
            __syncthreads();
        }
    }

    // ---- epilogue: bias + relu + store ----
    const float* brow = bias + s * UNITS + nb * NTILE;
#pragma unroll
    for (int mf = 0; mf < 4; mf++) {
        int r0 = mb * MTILE + wm * 64 + mf * 16 + (lid >> 2);
        float* o0 = out + ((size_t)r0 * SPLIT + s) * UNITS + nb * NTILE;
        float* o1 = o0 + (size_t)8 * SPLIT * UNITS;
#pragma unroll
        for (int nf = 0; nf < 4; nf++) {
            int c = wn * 32 + nf * 8 + 2 * (lid & 3);
            float2 bv = *(const float2*)(brow + c);
            float2 v0, v1;
            v0.x = fmaxf(acc[mf][nf][0] + bv.x, 0.f);
            v0.y = fmaxf(acc[mf][nf][1] + bv.y, 0.f);
            v1.x = fmaxf(acc[mf][nf][2] + bv.x, 0.f);
            v1.y = fmaxf(acc[mf][nf][3] + bv.y, 0.f);
            *(float2*)(o0 + c) = v0;
            *(float2*)(o1 + c) = v1;
        }
    }
}

// ---------------- launch ----------------
extern "C" void kernel_launch(void* const* d_in, const int* in_sizes, int n_in,
                              void* d_out, int out_size) {
    const float* x = (const float*)d_in[0];
    const float* W = (const float*)d_in[1];
    const float* b = (const float*)d_in[2];
    float* out = (float*)d_out;

    prep_w_kernel<<<dim3(8, 8, 32), dim3(32, 8)>>>(W);

    cudaFuncSetAttribute(lc_hmma_kernel, cudaFuncAttributeMaxDynamicSharedMemorySize, SM_TOTAL);
    lc_hmma_kernel<<<dim3((B_DIM / MTILE) * 2, SPLIT), 256, SM_TOTAL>>>(x, b, out);
}